// round 17
// baseline (speedup 1.0000x reference)
#include <cuda_runtime.h>
#include <math.h>
#include <float.h>

#define OUTD    12
#define N_VOX   1728              // 12*12*12
#define N_ROIS  128
#define NPAIR   (N_ROIS / 2)      // 64 packed ROI pairs
#define N_PTS   160000
#define NCH     64
#define KMAX    64                // cap on points per (roi,voxel); fallback handles overflow
#define NRV     (N_ROIS * N_VOX)  // 221184
#define NF4     (NRV * NCH / 4)   // 3,538,944 float4s in output

#define GRID    (N_PTS / 256)     // 625 blocks; 5/SM resident (740 slots)
#define NWARPS  (GRID * 8)        // 5000 warps in pool phase
#define QBUF    512               // per-block smem queue (expected ~27 used)

static_assert(N_PTS % 256 == 0, "exact grid");

typedef unsigned long long u64;

// Packed f32x2 ops (Blackwell sm_103a; FFMA2 only reachable via PTX).
#define PK2(out, lo, hi) \
    asm("mov.b64 %0, {%1, %2};" : "=l"(out) : "r"(__float_as_uint(lo)), "r"(__float_as_uint(hi)))
#define ADD2(out, a, b) asm("add.rn.f32x2 %0, %1, %2;" : "=l"(out) : "l"(a), "l"(b))
#define MUL2(out, a, b) asm("mul.rn.f32x2 %0, %1, %2;" : "=l"(out) : "l"(a), "l"(b))
#define FMA2(out, a, b, c) \
    asm("fma.rn.f32x2 %0, %1, %2, %3;" : "=l"(out) : "l"(a), "l"(b), "l"(c))
#define UNPK2(lo, hi, in) asm("mov.b64 {%0, %1}, %2;" : "=r"(lo), "=r"(hi) : "l"(in))

// Scratch (__device__ globals = sanctioned scratch; zero-initialized at load).
// Invariants restored every replay: d_count zeroed per entry in pool phase;
// d_qn/d_arrive/d_done reset by last block out.
__device__ int d_count[NRV];
__device__ __align__(16) int d_list[NRV * KMAX];   // slots 1.. (slot0 rides in queue)
__device__ int d_qn;
__device__ int d_arrive;
__device__ int d_done;
__device__ __align__(8) int2 d_queue[NRV];         // {rv, first_pid}

// ---------------------------------------------------------------------------
// Cold path for pool entries with n>1 (list merge) and n>KMAX (full rescan).
// __noinline__: ONE copy, out of the hot instruction stream.
// ---------------------------------------------------------------------------
__device__ __noinline__ float2 slow_entry(
    int rv, int n, int lane,
    const float* __restrict__ rois, const float* __restrict__ pts,
    const float* __restrict__ feat, float2 acc)
{
    float mx0 = acc.x, mx1 = acc.y;
    int mm = min(n, KMAX);
    const int* lst = &d_list[(size_t)rv * KMAX];
    int4 q4 = *(const int4*)lst;               // slots 0..3 (slot0 unused)
    {
        float2 v1, v2, v3;
        if (mm > 1) v1 = ((const float2*)(feat + (size_t)q4.y * NCH))[lane];
        if (mm > 2) v2 = ((const float2*)(feat + (size_t)q4.z * NCH))[lane];
        if (mm > 3) v3 = ((const float2*)(feat + (size_t)q4.w * NCH))[lane];
        if (mm > 1) { mx0 = fmaxf(mx0, v1.x); mx1 = fmaxf(mx1, v1.y); }
        if (mm > 2) { mx0 = fmaxf(mx0, v2.x); mx1 = fmaxf(mx1, v2.y); }
        if (mm > 3) { mx0 = fmaxf(mx0, v3.x); mx1 = fmaxf(mx1, v3.y); }
    }
    for (int j = 4; j < mm; j++) {
        int pid = lst[j];
        float2 v = ((const float2*)(feat + (size_t)pid * NCH))[lane];
        mx0 = fmaxf(mx0, v.x);
        mx1 = fmaxf(mx1, v.y);
    }
    if (n > KMAX) {
        // Correctness fallback (statistically never taken): rescan all points.
        int r = rv / N_VOX, vox = rv % N_VOX;
        int xi = vox / (OUTD * OUTD), yi = (vox / OUTD) % OUTD, zi = vox % OUTD;
        const float* R = rois + r * 7;
        float cx = R[0], cy = R[1], cz = R[2];
        float dx = R[3], dy = R[4], dz = R[5];
        float ry = R[6];
        float hdx = dx * 0.5f, hdy = dy * 0.5f, hdz = dz * 0.5f;
        float ca = cosf(-ry), sa = sinf(-ry);
        float vx = dx / (float)OUTD, vy = dy / (float)OUTD, vz = dz / (float)OUTD;
        for (int bb = 0; bb < N_PTS; bb += 32) {
            int pp = bb + lane;
            bool hit = false;
            {
                float sx = pts[3 * pp + 0] - cx;
                float sy = pts[3 * pp + 1] - cy;
                float szz = pts[3 * pp + 2] - cz;
                float lx = sx * ca - sy * sa;
                float ly = sx * sa + sy * ca;
                if ((lx > -hdx) && (lx < hdx) && (ly > -hdy) && (ly < hdy) &&
                    (fabsf(szz - hdz) <= hdz)) {
                    int xa = min(OUTD - 1, max(0, (int)floorf((lx + hdx) / vx)));
                    int ya = min(OUTD - 1, max(0, (int)floorf((ly + hdy) / vy)));
                    int za = min(OUTD - 1, max(0, (int)floorf(szz / vz)));
                    hit = (xa == xi) && (ya == yi) && (za == zi);
                }
            }
            unsigned mk = __ballot_sync(0xffffffffu, hit);
            while (mk) {
                int src = __ffs(mk) - 1;
                mk &= mk - 1;
                int pid = bb + src;
                float2 v = ((const float2*)(feat + (size_t)pid * NCH))[lane];
                mx0 = fmaxf(mx0, v.x);
                mx1 = fmaxf(mx1, v.y);
            }
        }
    }
    return make_float2(mx0, mx1);
}

// ---------------------------------------------------------------------------
// ONE persistent kernel. Phase 1: interleaved zero-fill + build with a
// PACKED f32x2 circle test (2 ROIs/iter). Grid barrier. Phase 2: worklist
// pool with all (<=4) entries batch-prefetched per warp (MLP=4 chains).
// ---------------------------------------------------------------------------
__global__ __launch_bounds__(256, 5) void fused_kernel(
    const float* __restrict__ rois, const float* __restrict__ pts,
    const float* __restrict__ feat, float* __restrict__ out)
{
    __shared__ float4 sP[NPAIR];   // {-cx0, -cx1, -cy0, -cy1} per ROI pair
    __shared__ float2 sR[NPAIR];   // {-r2_0, -r2_1} per ROI pair (with margin)
    __shared__ float4 sA[N_ROIS];  // {cx, cy, unused, cz}
    __shared__ float4 sB[N_ROIS];  // {cosa, sina, hdx, hdy}
    __shared__ float4 sC[N_ROIS];  // {hdz, vx, vy, vz}
    __shared__ int2   sQbuf[QBUF];
    __shared__ int    sQcnt;
    __shared__ int    sGbase;

    int t = threadIdx.x;
    int lane = t & 31;
    int wid  = t >> 5;
    int p = blockIdx.x * 256 + t;             // always < N_PTS (exact grid)

    float px = pts[3 * p + 0];
    float py = pts[3 * p + 1];
    float pz = pts[3 * p + 2];

    if (t == 0) sQcnt = 0;
    if (t < N_ROIS) {
        const float* R = rois + t * 7;
        float cx = R[0], cy = R[1], cz = R[2];
        float dx = R[3], dy = R[4], dz = R[5];
        float ry = R[6];
        float hdx = dx * 0.5f, hdy = dy * 0.5f, hdz = dz * 0.5f;
        float ca  = cosf(-ry), sa = sinf(-ry);
        sA[t] = make_float4(cx, cy, 0.f, cz);
        sB[t] = make_float4(ca, sa, hdx, hdy);
        sC[t] = make_float4(hdz, dx / (float)OUTD, dy / (float)OUTD, dz / (float)OUTD);
    }
    if (t < NPAIR) {
        const float* R0 = rois + (2 * t) * 7;
        const float* R1 = rois + (2 * t + 1) * 7;
        float hx0 = R0[3] * 0.5f, hy0 = R0[4] * 0.5f;
        float hx1 = R1[3] * 0.5f, hy1 = R1[4] * 0.5f;
        float r20 = (hx0 * hx0 + hy0 * hy0) * 1.0002f + 1e-6f;  // conservative
        float r21 = (hx1 * hx1 + hy1 * hy1) * 1.0002f + 1e-6f;
        sP[t] = make_float4(-R0[0], -R1[0], -R0[1], -R1[1]);
        sR[t] = make_float2(-r20, -r21);
    }
    __syncthreads();

    // ---------------- Phase 1: build + interleaved fill ----------------
    float4* o4 = (float4*)out;
    const float4 z = make_float4(0.f, 0.f, 0.f, 0.f);
    int fi = p;                                // fill cursor, stride N_PTS

    u64 px2, py2;
    PK2(px2, px, px);
    PK2(py2, py, py);

    for (int ppair = 0; ppair < NPAIR; ppair += 2) {
        // One interleaved zero store per 4 ROIs: the store queue drains
        // under the packed compute, hiding the 56.6MB LTS drain.
        if (fi < NF4) { __stcs(&o4[fi], z); fi += N_PTS; }

        #pragma unroll
        for (int u = 0; u < 2; u++) {
            int rp = ppair + u;
            float4 P = sP[rp];                 // broadcast LDS.128 (uniform rp)
            float2 Rm = sR[rp];
            u64 ncx2, ncy2, nr2, sx2, sy2, t2, d2, df;
            PK2(ncx2, P.x, P.y);
            PK2(ncy2, P.z, P.w);
            PK2(nr2, Rm.x, Rm.y);
            ADD2(sx2, px2, ncx2);              // {px-cx0, px-cx1}
            ADD2(sy2, py2, ncy2);
            MUL2(t2, sx2, sx2);
            FMA2(d2, sy2, sy2, t2);            // {d2_0, d2_1}
            ADD2(df, d2, nr2);                 // {d2_0-r2_0, d2_1-r2_1}
            unsigned lo, hi;
            UNPK2(lo, hi, df);
            if (((lo | hi) & 0x80000000u) == 0u) continue;   // both miss (~93%)

            // Rare: at least one candidate in this pair. Full exact test.
            #pragma unroll
            for (int h = 0; h < 2; h++) {
                if (!((h ? hi : lo) & 0x80000000u)) continue;
                int r = 2 * rp + h;
                float4 A = sA[r];
                float4 B = sB[r];
                float4 C = sC[r];
                float sx = px - A.x;
                float sy = py - A.y;
                float sz = pz - A.w;
                float lx = sx * B.x - sy * B.y;
                float ly = sx * B.y + sy * B.x;
                bool in_box = (lx > -B.z) && (lx < B.z) &&
                              (ly > -B.w) && (ly < B.w) &&
                              (fabsf(sz - C.x) <= C.x);
                if (!in_box) continue;
                int xi = min(OUTD - 1, max(0, (int)floorf((lx + B.z) / C.y)));
                int yi = min(OUTD - 1, max(0, (int)floorf((ly + B.w) / C.z)));
                int zi = min(OUTD - 1, max(0, (int)floorf(sz / C.w)));
                int rv = r * N_VOX + xi * (OUTD * OUTD) + yi * OUTD + zi;
                int c = atomicAdd(&d_count[rv], 1);
                if (c == 0) {                  // unique first inserter
                    int qi = atomicAdd(&sQcnt, 1);     // smem, no L2 hotspot
                    if (qi < QBUF) {
                        sQbuf[qi] = make_int2(rv, p);
                    } else {                   // overflow fallback (never taken)
                        int g = atomicAdd(&d_qn, 1);
                        d_queue[g] = make_int2(rv, p);
                    }
                } else if (c < KMAX) {
                    d_list[rv * KMAX + c] = p; // slots 1..KMAX-1
                }
            }
        }
    }
    for (; fi < NF4; fi += N_PTS) __stcs(&o4[fi], z);   // safety tail

    // Flush smem queue: one global atomic per block, coalesced copy-out.
    __syncthreads();
    int cnt = min(sQcnt, QBUF);
    if (t == 0) sGbase = atomicAdd(&d_qn, cnt);
    __syncthreads();
    int gbase = sGbase;
    for (int j = t; j < cnt; j += 256)
        d_queue[gbase + j] = sQbuf[j];

    // ---------------- Grid barrier (all 625 blocks resident) ----------------
    __threadfence();                           // release phase-1 writes
    __syncthreads();
    if (t == 0) {
        atomicAdd(&d_arrive, 1);
        volatile int* va = &d_arrive;
        while (*va < GRID) __nanosleep(64);
    }
    __syncthreads();
    __threadfence();                           // acquire phase-1 writes

    // ---------------- Phase 2: batched worklist pool ----------------
    int qn = d_qn;                             // final
    int gw = blockIdx.x * 8 + wid;

    int   rv[4], pid[4], n[4];
    float2 v[4];
    #pragma unroll
    for (int k = 0; k < 4; k++) {              // queue words (4 independent)
        rv[k] = -1;
        int idx = gw + k * NWARPS;
        if (idx < qn) { int2 q = d_queue[idx]; rv[k] = q.x; pid[k] = q.y; }
    }
    #pragma unroll
    for (int k = 0; k < 4; k++)                // counts (4 independent)
        n[k] = (rv[k] >= 0) ? d_count[rv[k]] : 0;
    #pragma unroll
    for (int k = 0; k < 4; k++) {              // feature rows (4 independent)
        v[k] = make_float2(0.f, 0.f);
        if (rv[k] >= 0)
            v[k] = ((const float2*)(feat + (size_t)pid[k] * NCH))[lane];
    }
    #pragma unroll
    for (int k = 0; k < 4; k++) {
        if (rv[k] < 0) continue;
        if (lane == 0) d_count[rv[k]] = 0;     // self-clean for next replay
        float2 acc = v[k];                     // n==1 (~94%): row is the answer
        if (n[k] > 1)
            acc = slow_entry(rv[k], n[k], lane, rois, pts, feat, acc);
        __stcs(&((float2*)(out + (size_t)rv[k] * NCH))[lane], acc);
    }
    // Tail (only if qn > 4*NWARPS = 20000; statistically never taken).
    for (int idx = gw + 4 * NWARPS; idx < qn; idx += NWARPS) {
        int2 q = d_queue[idx];
        int nn = d_count[q.x];
        if (lane == 0) d_count[q.x] = 0;
        float2 acc = ((const float2*)(feat + (size_t)q.y * NCH))[lane];
        if (nn > 1) acc = slow_entry(q.x, nn, lane, rois, pts, feat, acc);
        __stcs(&((float2*)(out + (size_t)q.x * NCH))[lane], acc);
    }

    // Last block out resets all counters (race-free ticket).
    __syncthreads();
    if (t == 0) {
        __threadfence();
        int ticket = atomicAdd(&d_done, 1);
        if (ticket == GRID - 1) {
            d_qn = 0;
            d_arrive = 0;
            d_done = 0;
        }
    }
}

// ---------------------------------------------------------------------------
extern "C" void kernel_launch(void* const* d_in, const int* in_sizes, int n_in,
                              void* d_out, int out_size)
{
    const float* rois = (const float*)d_in[0];       // (128, 7)
    const float* pts  = (const float*)d_in[1];       // (160000, 3)
    const float* feat = (const float*)d_in[2];       // (160000, 64)
    float* out = (float*)d_out;                      // (128, 12, 12, 12, 64)

    fused_kernel<<<GRID, 256>>>(rois, pts, feat, out);   // single launch
}